// round 1
// baseline (speedup 1.0000x reference)
#include <cuda_runtime.h>

#define FULLMASK 0xffffffffu

static constexpr int B_V   = 8192;
static constexpr int KN    = 64;
static constexpr int TASKS = 2 * B_V;   // 16384 (vertex, side) tasks
static constexpr int IN2   = 132;       // device feature dim (20 dense + 7*16 emb)
static constexpr int XDIM  = 96;        // [h(64) | ch_v(32)]
static constexpr int HID   = 84;        // attention hidden

// Scratch (no cudaMalloc allowed)
__device__ float g_mean[TASKS * IN2];   // 8.6 MB
__device__ float g_x[TASKS * XDIM];     // 6.3 MB
__device__ float g_hid[TASKS * HID];    // 5.5 MB

// ---------------------------------------------------------------------------
// Kernel 1: masked mean of neighbor features. One warp per (vertex, side).
// Lane c owns feature dims [4c, 4c+4); lane 0 additionally owns dims [128,132).
// dims [0,20): device_dense row; dims [20+16t, 20+16t+16): table t row.
// ---------------------------------------------------------------------------
__global__ void __launch_bounds__(256) k_mean(
    const float* __restrict__ device_dense,
    const int*   __restrict__ device_cat,
    const float* __restrict__ t0, const float* __restrict__ t1,
    const float* __restrict__ t2, const float* __restrict__ t3,
    const float* __restrict__ t4, const float* __restrict__ t5,
    const float* __restrict__ t6,
    const int* __restrict__ bot_neibrs, const int* __restrict__ normal_neibrs,
    const int* __restrict__ bot_counts, const int* __restrict__ normal_counts)
{
    int task = blockIdx.x * 8 + (threadIdx.x >> 5);
    int lane = threadIdx.x & 31;
    int b    = task >> 1;
    int side = task & 1;

    const int* neib = side ? normal_neibrs : bot_neibrs;
    int cnt = side ? normal_counts[b] : bot_counts[b];
    cnt = min(max(cnt, 1), KN);

    // Coalesced preload of all 64 neighbor ids (2 regs per lane)
    int i0 = neib[b * KN + lane];
    int i1 = neib[b * KN + 32 + lane];

    // Per-lane chunk mapping (computed once)
    int  c       = lane;
    bool isDense = (c < 5);
    int  m       = (c < 5) ? 0 : (c - 5);
    int  t       = m >> 2;           // table id for emb lanes (0 for dense lanes)
    int  e4      = (m & 3) * 4;      // element offset within table row
    const float* base;
    switch (t) {
        case 0: base = t0; break; case 1: base = t1; break;
        case 2: base = t2; break; case 3: base = t3; break;
        case 4: base = t4; break; case 5: base = t5; break;
        default: base = t6; break;
    }

    float4 acc  = make_float4(0.f, 0.f, 0.f, 0.f);
    float4 acc2 = make_float4(0.f, 0.f, 0.f, 0.f);   // lane 0: dims 128..131

    #pragma unroll 4
    for (int n = 0; n < cnt; ++n) {
        int idx  = __shfl_sync(FULLMASK, (n & 32) ? i1 : i0, n & 31);
        // one coalesced (mostly-broadcast) load of this neighbor's 7 cat ids
        int creg = __ldg(device_cat + (size_t)idx * 7 + (lane < 7 ? lane : 6));
        int cat  = __shfl_sync(FULLMASK, creg, t);
        int cat6 = __shfl_sync(FULLMASK, creg, 6);

        const float4* p = isDense
            ? reinterpret_cast<const float4*>(device_dense + (size_t)idx * 20 + 4 * c)
            : reinterpret_cast<const float4*>(base + (size_t)cat * 16 + e4);
        float4 v = __ldg(p);
        acc.x += v.x; acc.y += v.y; acc.z += v.z; acc.w += v.w;

        if (lane == 0) {
            float4 v2 = __ldg(reinterpret_cast<const float4*>(t6 + (size_t)cat6 * 16 + 12));
            acc2.x += v2.x; acc2.y += v2.y; acc2.z += v2.z; acc2.w += v2.w;
        }
    }

    float inv = 1.0f / (float)cnt;
    float4 o = make_float4(acc.x * inv, acc.y * inv, acc.z * inv, acc.w * inv);
    *reinterpret_cast<float4*>(g_mean + (size_t)task * IN2 + 4 * c) = o;
    if (lane == 0) {
        float4 o2 = make_float4(acc2.x * inv, acc2.y * inv, acc2.z * inv, acc2.w * inv);
        *reinterpret_cast<float4*>(g_mean + (size_t)task * IN2 + 128) = o2;
    }
}

// ---------------------------------------------------------------------------
// Kernel 2: channel self features into g_x[:, 64:96] (same for both sides)
// ---------------------------------------------------------------------------
__global__ void __launch_bounds__(256) k_chv(
    const float* __restrict__ channel_dense,
    const float* __restrict__ channel_id_emb,
    const int*   __restrict__ channel_ids,
    const int*   __restrict__ vertices)
{
    int gid = blockIdx.x * blockDim.x + threadIdx.x;
    if (gid >= B_V * 32) return;
    int b = gid >> 5, j = gid & 31;
    int v = vertices[b];
    float val;
    if (j < 16) val = channel_dense[(size_t)v * 16 + j];
    else        val = channel_id_emb[(size_t)channel_ids[v] * 16 + (j - 16)];
    g_x[(size_t)(2 * b)     * XDIM + 64 + j] = val;
    g_x[(size_t)(2 * b + 1) * XDIM + 64 + j] = val;
}

// ---------------------------------------------------------------------------
// Kernel 3/4: small tiled SGEMM. C[M,N] = op(A[M,K] @ B[K,N] + bias), optional relu.
// BM=64 rows per CTA, 256 threads; warp owns 8 rows, lane owns cols {lane+32j}.
// ---------------------------------------------------------------------------
template<int BN>
__global__ void __launch_bounds__(256) k_sgemm(
    const float* __restrict__ A, int lda, int K,
    const float* __restrict__ Bw, int ldb, int N,
    const float* __restrict__ bias,
    float* __restrict__ C, int ldc, int doRelu)
{
    constexpr int NCOLS = BN / 32;
    __shared__ float As[16][64];
    __shared__ float Bs[16][BN];

    int tid = threadIdx.x, warp = tid >> 5, lane = tid & 31;
    int row0 = blockIdx.x * 64;

    float acc[8][NCOLS];
    #pragma unroll
    for (int i = 0; i < 8; ++i)
        #pragma unroll
        for (int j = 0; j < NCOLS; ++j) acc[i][j] = 0.f;

    for (int k0 = 0; k0 < K; k0 += 16) {
        // Stage A tile (transposed to As[k][row]); zero-fill past K
        {
            int r = tid >> 2, kq = (tid & 3) * 4;
            float4 a = make_float4(0.f, 0.f, 0.f, 0.f);
            if (k0 + kq < K)
                a = *reinterpret_cast<const float4*>(A + (size_t)(row0 + r) * lda + k0 + kq);
            As[kq + 0][r] = a.x; As[kq + 1][r] = a.y;
            As[kq + 2][r] = a.z; As[kq + 3][r] = a.w;
        }
        // Stage B tile; zero-fill past K or N
        for (int i = tid; i < 16 * BN / 4; i += 256) {
            int k  = i / (BN / 4);
            int c4 = (i % (BN / 4)) * 4;
            float4 bv = make_float4(0.f, 0.f, 0.f, 0.f);
            if (k0 + k < K && c4 < N)
                bv = *reinterpret_cast<const float4*>(Bw + (size_t)(k0 + k) * ldb + c4);
            *reinterpret_cast<float4*>(&Bs[k][c4]) = bv;
        }
        __syncthreads();

        #pragma unroll
        for (int k = 0; k < 16; ++k) {
            float4 a0 = *reinterpret_cast<const float4*>(&As[k][warp * 8]);
            float4 a1 = *reinterpret_cast<const float4*>(&As[k][warp * 8 + 4]);
            float av[8] = {a0.x, a0.y, a0.z, a0.w, a1.x, a1.y, a1.z, a1.w};
            float bv[NCOLS];
            #pragma unroll
            for (int j = 0; j < NCOLS; ++j) bv[j] = Bs[k][lane + 32 * j];
            #pragma unroll
            for (int i = 0; i < 8; ++i)
                #pragma unroll
                for (int j = 0; j < NCOLS; ++j)
                    acc[i][j] += av[i] * bv[j];
        }
        __syncthreads();
    }

    #pragma unroll
    for (int j = 0; j < NCOLS; ++j) {
        int col = lane + 32 * j;
        if (col < N) {
            float bb = bias[col];
            #pragma unroll
            for (int i = 0; i < 8; ++i) {
                float v = acc[i][j] + bb;
                if (doRelu) v = fmaxf(v, 0.f);
                C[(size_t)(row0 + warp * 8 + i) * ldc + col] = v;
            }
        }
    }
}

// ---------------------------------------------------------------------------
// Kernel 5: scores, softmax(2), convex combine, self-linear, relu, output.
// One warp per vertex.
// ---------------------------------------------------------------------------
__global__ void __launch_bounds__(256) k_final(
    const float* __restrict__ W_self, const float* __restrict__ b_self,
    const float* __restrict__ W_attn2, const float* __restrict__ b_attn2,
    float* __restrict__ out)
{
    int b    = blockIdx.x * 8 + (threadIdx.x >> 5);
    int lane = threadIdx.x & 31;

    float s[2];
    #pragma unroll
    for (int sd = 0; sd < 2; ++sd) {
        const float* hrow = g_hid + (size_t)(2 * b + sd) * HID;
        float p = 0.f;
        for (int i = lane; i < HID; i += 32) p += hrow[i] * W_attn2[i];
        #pragma unroll
        for (int o = 16; o; o >>= 1) p += __shfl_xor_sync(FULLMASK, p, o);
        s[sd] = p + b_attn2[0];
    }
    float mx = fmaxf(s[0], s[1]);
    float e0 = __expf(s[0] - mx), e1 = __expf(s[1] - mx);
    float den = e0 + e1;
    float a0 = e0 / den, a1 = e1 / den;

    const float* x0 = g_x + (size_t)(2 * b)     * XDIM;
    const float* x1 = g_x + (size_t)(2 * b + 1) * XDIM;
    #pragma unroll
    for (int j = 0; j < 2; ++j) {
        int d = lane + 32 * j;
        out[(size_t)b * 128 + d] = fmaxf(a0 * x0[d] + a1 * x1[d], 0.f);
    }

    // ch_self = relu(ch_v @ W_self + b_self); lane owns output cols {2l, 2l+1}
    float chv = x0[64 + lane];
    float r0 = b_self[2 * lane], r1 = b_self[2 * lane + 1];
    #pragma unroll
    for (int d = 0; d < 32; ++d) {
        float xv = __shfl_sync(FULLMASK, chv, d);
        float2 w = *reinterpret_cast<const float2*>(W_self + d * 64 + 2 * lane);
        r0 += xv * w.x; r1 += xv * w.y;
    }
    out[(size_t)b * 128 + 64 + 2 * lane] = fmaxf(r0, 0.f);
    out[(size_t)b * 128 + 65 + 2 * lane] = fmaxf(r1, 0.f);
}

// ---------------------------------------------------------------------------
extern "C" void kernel_launch(void* const* d_in, const int* in_sizes, int n_in,
                              void* d_out, int out_size)
{
    const float* channel_dense  = (const float*)d_in[0];
    const float* device_dense   = (const float*)d_in[1];
    const float* channel_id_emb = (const float*)d_in[2];
    const float* t0 = (const float*)d_in[3];   // lang
    const float* t1 = (const float*)d_in[4];   // plat
    const float* t2 = (const float*)d_in[5];   // os
    const float* t3 = (const float*)d_in[6];   // country
    const float* t4 = (const float*)d_in[7];   // carrier
    const float* t5 = (const float*)d_in[8];   // brand
    const float* t6 = (const float*)d_in[9];   // plat_os
    const float* W_agg   = (const float*)d_in[10];
    const float* b_agg   = (const float*)d_in[11];
    const float* W_self  = (const float*)d_in[12];
    const float* b_self  = (const float*)d_in[13];
    const float* W_attn  = (const float*)d_in[14];
    const float* b_attn  = (const float*)d_in[15];
    const float* W_attn2 = (const float*)d_in[16];
    const float* b_attn2 = (const float*)d_in[17];
    const int* channel_ids   = (const int*)d_in[18];
    const int* device_cat    = (const int*)d_in[19];
    const int* vertices      = (const int*)d_in[20];
    const int* bot_neibrs    = (const int*)d_in[21];
    const int* normal_neibrs = (const int*)d_in[22];
    const int* bot_counts    = (const int*)d_in[23];
    const int* normal_counts = (const int*)d_in[24];
    float* out = (float*)d_out;

    float *pmean, *px, *phid;
    cudaGetSymbolAddress((void**)&pmean, g_mean);
    cudaGetSymbolAddress((void**)&px,    g_x);
    cudaGetSymbolAddress((void**)&phid,  g_hid);

    // 1) neighbor masked means
    k_mean<<<TASKS / 8, 256>>>(device_dense, device_cat,
                               t0, t1, t2, t3, t4, t5, t6,
                               bot_neibrs, normal_neibrs, bot_counts, normal_counts);
    // 2) channel self features into g_x[:,64:96]
    k_chv<<<(B_V * 32) / 256, 256>>>(channel_dense, channel_id_emb, channel_ids, vertices);
    // 3) h = mean @ W_agg + b_agg  -> g_x[:,0:64]
    k_sgemm<64><<<TASKS / 64, 256>>>(pmean, IN2, IN2, W_agg, 64, 64, b_agg, px, XDIM, 0);
    // 4) hid = relu(x @ W_attn + b_attn) -> g_hid
    k_sgemm<96><<<TASKS / 64, 256>>>(px, XDIM, XDIM, W_attn, HID, HID, b_attn, phid, HID, 1);
    // 5) finalize
    k_final<<<B_V / 8, 256>>>(W_self, b_self, W_attn2, b_attn2, out);
}

// round 2
// speedup vs baseline: 1.1585x; 1.1585x over previous
#include <cuda_runtime.h>

#define FULLMASK 0xffffffffu

static constexpr int B_V   = 8192;
static constexpr int KN    = 64;
static constexpr int TASKS = 2 * B_V;   // 16384 (vertex, side) tasks
static constexpr int IN2   = 132;       // device feature dim (20 dense + 7*16 emb)
static constexpr int HID   = 84;

// Scratch (no cudaMalloc allowed)
__device__ float g_mean[TASKS * IN2];   // 8.6 MB

// ---------------------------------------------------------------------------
// Kernel 1: masked mean of neighbor features. One warp per (vertex, side).
// Stage A: prefetch all needed cat ids (7 per neighbor) into smem with
//          coalesced, dependency-free loads (high MLP).
// Stage B: lane c owns feature dims [4c,4c+4); lane 0 also dims [128,132).
//          Per neighbor: SHFL idx -> LDS cat -> one independent LDG.128.
// ---------------------------------------------------------------------------
__global__ void __launch_bounds__(256) k_mean(
    const float* __restrict__ device_dense,
    const int*   __restrict__ device_cat,
    const float* __restrict__ t0, const float* __restrict__ t1,
    const float* __restrict__ t2, const float* __restrict__ t3,
    const float* __restrict__ t4, const float* __restrict__ t5,
    const float* __restrict__ t6,
    const int* __restrict__ bot_neibrs, const int* __restrict__ normal_neibrs,
    const int* __restrict__ bot_counts, const int* __restrict__ normal_counts)
{
    __shared__ int sCat[8][KN * 8];   // [warp][n*8+t], 16 KB

    int w    = threadIdx.x >> 5;
    int lane = threadIdx.x & 31;
    int task = blockIdx.x * 8 + w;
    int b    = task >> 1;
    int side = task & 1;

    const int* neib = side ? normal_neibrs : bot_neibrs;
    int cnt = side ? normal_counts[b] : bot_counts[b];
    cnt = min(max(cnt, 1), KN);

    // Coalesced preload of all 64 neighbor ids (2 regs per lane)
    int i0 = neib[b * KN + lane];
    int i1 = neib[b * KN + 32 + lane];

    // --- Stage A: prefetch cat ids, flat-indexed & coalesced, no dep chains ---
    int tot = cnt * 7;
    for (int r = 0; r * 32 < tot; ++r) {
        int flat = r * 32 + lane;
        int n = flat / 7;
        int t = flat - n * 7;
        int nn = min(n, KN - 1);
        int a0 = __shfl_sync(FULLMASK, i0, nn & 31);
        int a1 = __shfl_sync(FULLMASK, i1, nn & 31);
        int idx = (nn < 32) ? a0 : a1;
        if (n < KN)
            sCat[w][n * 8 + t] = __ldg(device_cat + (size_t)idx * 7 + t);
    }
    __syncwarp();

    // --- per-lane chunk mapping ---
    int  c       = lane;
    bool isDense = (c < 5);
    int  m       = (c < 5) ? 0 : (c - 5);
    int  t       = m >> 2;
    int  e4      = (m & 3) * 4;
    const float* base;
    switch (t) {
        case 0: base = t0; break; case 1: base = t1; break;
        case 2: base = t2; break; case 3: base = t3; break;
        case 4: base = t4; break; case 5: base = t5; break;
        default: base = t6; break;
    }

    float4 acc  = make_float4(0.f, 0.f, 0.f, 0.f);
    float4 acc2 = make_float4(0.f, 0.f, 0.f, 0.f);

    #pragma unroll 4
    for (int n = 0; n < cnt; ++n) {
        int a0 = __shfl_sync(FULLMASK, i0, n & 31);
        int a1 = __shfl_sync(FULLMASK, i1, n & 31);
        int idx = (n & 32) ? a1 : a0;

        int cat = sCat[w][n * 8 + t];
        const float4* p = isDense
            ? reinterpret_cast<const float4*>(device_dense + (size_t)idx * 20 + 4 * c)
            : reinterpret_cast<const float4*>(base + (size_t)cat * 16 + e4);
        float4 v = __ldg(p);
        acc.x += v.x; acc.y += v.y; acc.z += v.z; acc.w += v.w;

        if (lane == 0) {
            int cat6 = sCat[w][n * 8 + 6];
            float4 v2 = __ldg(reinterpret_cast<const float4*>(t6 + (size_t)cat6 * 16 + 12));
            acc2.x += v2.x; acc2.y += v2.y; acc2.z += v2.z; acc2.w += v2.w;
        }
    }

    float inv = 1.0f / (float)cnt;
    float4 o = make_float4(acc.x * inv, acc.y * inv, acc.z * inv, acc.w * inv);
    *reinterpret_cast<float4*>(g_mean + (size_t)task * IN2 + 4 * c) = o;
    if (lane == 0) {
        float4 o2 = make_float4(acc2.x * inv, acc2.y * inv, acc2.z * inv, acc2.w * inv);
        *reinterpret_cast<float4*>(g_mean + (size_t)task * IN2 + 128) = o2;
    }
}

// ---------------------------------------------------------------------------
// Kernel 2: fused post-processing. 512 CTAs x 256 thr; CTA = 32 tasks (16 verts).
// All weights in smem. Phase1: h = mean@W_agg + b (h stored transposed in smem).
// Phase2: hid = relu([h|chv]@W_attn + b), score = hid . W_attn2.
// Phase3: softmax(2), convex combine, self-linear, relu, write out[B,128].
// ---------------------------------------------------------------------------
static constexpr int BM = 32;   // tasks per CTA

// smem layout (in floats)
static constexpr int O_WAGG  = 0;                       // [132][64]
static constexpr int O_WATT  = O_WAGG  + 132 * 64;      // [96][84]
static constexpr int O_WSELF = O_WATT  + 96 * 84;       // [32][64]
static constexpr int O_W2    = O_WSELF + 32 * 64;       // [84] pad 96
static constexpr int O_BAGG  = O_W2    + 96;            // [64]
static constexpr int O_BATT  = O_BAGG  + 64;            // [84] pad 96
static constexpr int O_BSELF = O_BATT  + 96;            // [64]
static constexpr int O_B2    = O_BSELF + 64;            // [1] pad 16
static constexpr int O_OVER  = O_B2    + 16;            // overlay: sA [132][36]
static constexpr int SA_LD   = 36;
static constexpr int O_SCORE = O_OVER  + 96 * SA_LD;    // 32 scores (inside overlay tail)
static constexpr int SMEM_FLOATS = O_OVER + 132 * SA_LD;
static constexpr int SMEM_BYTES  = SMEM_FLOATS * 4;     // ~94.6 KB

__global__ void __launch_bounds__(256) k_fused(
    const float* __restrict__ W_agg,  const float* __restrict__ b_agg,
    const float* __restrict__ W_attn, const float* __restrict__ b_attn,
    const float* __restrict__ W_attn2,const float* __restrict__ b_attn2,
    const float* __restrict__ W_self, const float* __restrict__ b_self,
    const float* __restrict__ channel_dense,
    const float* __restrict__ channel_id_emb,
    const int*   __restrict__ channel_ids,
    const int*   __restrict__ vertices,
    float* __restrict__ out)
{
    extern __shared__ float sm[];
    int tid  = threadIdx.x;
    int warp = tid >> 5;
    int lane = tid & 31;
    int tbase = blockIdx.x * BM;        // first task of this CTA
    int vbase = blockIdx.x * (BM / 2);  // first vertex

    // ---- load weights (vectorized where contiguous) ----
    for (int e = tid; e < (132 * 64) / 4; e += 256)
        reinterpret_cast<float4*>(sm + O_WAGG)[e] = reinterpret_cast<const float4*>(W_agg)[e];
    for (int e = tid; e < (96 * 84) / 4; e += 256)
        reinterpret_cast<float4*>(sm + O_WATT)[e] = reinterpret_cast<const float4*>(W_attn)[e];
    for (int e = tid; e < (32 * 64) / 4; e += 256)
        reinterpret_cast<float4*>(sm + O_WSELF)[e] = reinterpret_cast<const float4*>(W_self)[e];
    if (tid < 84) sm[O_W2 + tid]   = W_attn2[tid];
    if (tid < 64) sm[O_BAGG + tid] = b_agg[tid];
    if (tid >= 64 && tid < 148) sm[O_BATT + tid - 64] = b_attn[tid - 64];
    if (tid >= 148 && tid < 212) sm[O_BSELF + tid - 148] = b_self[tid - 148];
    if (tid == 212) sm[O_B2] = b_attn2[0];

    // ---- stage A (mean rows, transposed): sA[k][row] ----
    float* sA = sm + O_OVER;
    for (int e = tid; e < BM * 33; e += 256) {
        int row = e / 33, cch = e - row * 33;
        float4 v = *reinterpret_cast<const float4*>(g_mean + (size_t)(tbase + row) * IN2 + cch * 4);
        sA[(4 * cch + 0) * SA_LD + row] = v.x;
        sA[(4 * cch + 1) * SA_LD + row] = v.y;
        sA[(4 * cch + 2) * SA_LD + row] = v.z;
        sA[(4 * cch + 3) * SA_LD + row] = v.w;
    }
    __syncthreads();

    // ---- phase 1: h[row][64], warp owns rows warp*4..+4, lane owns cols lane, lane+32
    float acc1[4][2];
    #pragma unroll
    for (int r = 0; r < 4; ++r) { acc1[r][0] = 0.f; acc1[r][1] = 0.f; }
    {
        const float* wa = sm + O_WAGG;
        #pragma unroll 4
        for (int k = 0; k < IN2; ++k) {
            float4 av = *reinterpret_cast<const float4*>(&sA[k * SA_LD + warp * 4]);
            float b0 = wa[k * 64 + lane];
            float b1 = wa[k * 64 + lane + 32];
            acc1[0][0] += av.x * b0; acc1[0][1] += av.x * b1;
            acc1[1][0] += av.y * b0; acc1[1][1] += av.y * b1;
            acc1[2][0] += av.z * b0; acc1[2][1] += av.z * b1;
            acc1[3][0] += av.w * b0; acc1[3][1] += av.w * b1;
        }
    }
    __syncthreads();   // done reading sA; overlay becomes sHT

    // ---- write h(+bias) transposed: sHT[k=col][row]; fill chv rows 64..95 ----
    float* sHT = sm + O_OVER;   // [96][SA_LD]
    {
        float ba0 = sm[O_BAGG + lane], ba1 = sm[O_BAGG + lane + 32];
        #pragma unroll
        for (int r = 0; r < 4; ++r) {
            int row = warp * 4 + r;
            sHT[lane * SA_LD + row]        = acc1[r][0] + ba0;
            sHT[(lane + 32) * SA_LD + row] = acc1[r][1] + ba1;
        }
    }
    for (int e = tid; e < (BM / 2) * 32; e += 256) {
        int i = e >> 5, j = e & 31;
        int v = vertices[vbase + i];
        float val = (j < 16) ? channel_dense[(size_t)v * 16 + j]
                             : channel_id_emb[(size_t)channel_ids[v] * 16 + (j - 16)];
        sHT[(64 + j) * SA_LD + 2 * i]     = val;
        sHT[(64 + j) * SA_LD + 2 * i + 1] = val;
    }
    __syncthreads();

    // ---- phase 2: hid = relu(z @ W_attn + b); score = hid . W_attn2 ----
    float acc2[4][3];
    #pragma unroll
    for (int r = 0; r < 4; ++r) { acc2[r][0] = 0.f; acc2[r][1] = 0.f; acc2[r][2] = 0.f; }
    {
        const float* wt = sm + O_WATT;
        bool has3 = (lane < HID - 64);
        #pragma unroll 4
        for (int k = 0; k < 96; ++k) {
            float4 av = *reinterpret_cast<const float4*>(&sHT[k * SA_LD + warp * 4]);
            float w0 = wt[k * HID + lane];
            float w1 = wt[k * HID + lane + 32];
            float w2v = has3 ? wt[k * HID + lane + 64] : 0.f;
            acc2[0][0] += av.x * w0; acc2[0][1] += av.x * w1; acc2[0][2] += av.x * w2v;
            acc2[1][0] += av.y * w0; acc2[1][1] += av.y * w1; acc2[1][2] += av.y * w2v;
            acc2[2][0] += av.z * w0; acc2[2][1] += av.z * w1; acc2[2][2] += av.z * w2v;
            acc2[3][0] += av.w * w0; acc2[3][1] += av.w * w1; acc2[3][2] += av.w * w2v;
        }
    }
    {
        float bt0 = sm[O_BATT + lane], bt1 = sm[O_BATT + lane + 32];
        float bt2 = (lane < HID - 64) ? sm[O_BATT + lane + 64] : 0.f;
        float wv0 = sm[O_W2 + lane],  wv1 = sm[O_W2 + lane + 32];
        float wv2 = (lane < HID - 64) ? sm[O_W2 + lane + 64] : 0.f;
        float p[4];
        #pragma unroll
        for (int r = 0; r < 4; ++r) {
            p[r] = fmaxf(acc2[r][0] + bt0, 0.f) * wv0
                 + fmaxf(acc2[r][1] + bt1, 0.f) * wv1
                 + fmaxf(acc2[r][2] + bt2, 0.f) * wv2;
        }
        #pragma unroll
        for (int o = 16; o; o >>= 1) {
            #pragma unroll
            for (int r = 0; r < 4; ++r) p[r] += __shfl_xor_sync(FULLMASK, p[r], o);
        }
        if (lane == 0) {
            #pragma unroll
            for (int r = 0; r < 4; ++r) sm[O_SCORE + warp * 4 + r] = p[r];
        }
    }
    __syncthreads();

    // ---- phase 3: per vertex: softmax(2), combine, self-linear, relu, store ----
    #pragma unroll
    for (int s = 0; s < 2; ++s) {
        int vl = warp * 2 + s;              // local vertex 0..15
        int vg = vbase + vl;                // global vertex
        float s0 = sm[O_SCORE + 2 * vl];
        float s1 = sm[O_SCORE + 2 * vl + 1];
        float mx = fmaxf(s0, s1);
        float e0 = __expf(s0 - mx), e1 = __expf(s1 - mx);
        float a0 = e0 / (e0 + e1), a1 = 1.f - e0 / (e0 + e1);

        int r0i = 2 * vl, r1i = 2 * vl + 1;
        float g0 = a0 * sHT[lane * SA_LD + r0i]        + a1 * sHT[lane * SA_LD + r1i];
        float g1 = a0 * sHT[(lane + 32) * SA_LD + r0i] + a1 * sHT[(lane + 32) * SA_LD + r1i];
        out[(size_t)vg * 128 + lane]      = fmaxf(g0, 0.f);
        out[(size_t)vg * 128 + lane + 32] = fmaxf(g1, 0.f);

        float r0 = sm[O_BSELF + lane], r1 = sm[O_BSELF + lane + 32];
        const float* ws = sm + O_WSELF;
        #pragma unroll
        for (int d = 0; d < 32; ++d) {
            float xv = sHT[(64 + d) * SA_LD + r0i];   // broadcast
            r0 += xv * ws[d * 64 + lane];
            r1 += xv * ws[d * 64 + lane + 32];
        }
        out[(size_t)vg * 128 + 64 + lane] = fmaxf(r0, 0.f);
        out[(size_t)vg * 128 + 96 + lane] = fmaxf(r1, 0.f);
    }
}

// ---------------------------------------------------------------------------
extern "C" void kernel_launch(void* const* d_in, const int* in_sizes, int n_in,
                              void* d_out, int out_size)
{
    const float* channel_dense  = (const float*)d_in[0];
    const float* device_dense   = (const float*)d_in[1];
    const float* channel_id_emb = (const float*)d_in[2];
    const float* t0 = (const float*)d_in[3];
    const float* t1 = (const float*)d_in[4];
    const float* t2 = (const float*)d_in[5];
    const float* t3 = (const float*)d_in[6];
    const float* t4 = (const float*)d_in[7];
    const float* t5 = (const float*)d_in[8];
    const float* t6 = (const float*)d_in[9];
    const float* W_agg   = (const float*)d_in[10];
    const float* b_agg   = (const float*)d_in[11];
    const float* W_self  = (const float*)d_in[12];
    const float* b_self  = (const float*)d_in[13];
    const float* W_attn  = (const float*)d_in[14];
    const float* b_attn  = (const float*)d_in[15];
    const float* W_attn2 = (const float*)d_in[16];
    const float* b_attn2 = (const float*)d_in[17];
    const int* channel_ids   = (const int*)d_in[18];
    const int* device_cat    = (const int*)d_in[19];
    const int* vertices      = (const int*)d_in[20];
    const int* bot_neibrs    = (const int*)d_in[21];
    const int* normal_neibrs = (const int*)d_in[22];
    const int* bot_counts    = (const int*)d_in[23];
    const int* normal_counts = (const int*)d_in[24];
    float* out = (float*)d_out;

    static bool attr_set = false;
    if (!attr_set) {
        cudaFuncSetAttribute(k_fused, cudaFuncAttributeMaxDynamicSharedMemorySize, SMEM_BYTES);
        attr_set = true;
    }

    k_mean<<<TASKS / 8, 256>>>(device_dense, device_cat,
                               t0, t1, t2, t3, t4, t5, t6,
                               bot_neibrs, normal_neibrs, bot_counts, normal_counts);

    k_fused<<<TASKS / BM, 256, SMEM_BYTES>>>(
        W_agg, b_agg, W_attn, b_attn, W_attn2, b_attn2, W_self, b_self,
        channel_dense, channel_id_emb, channel_ids, vertices, out);
}